// round 8
// baseline (speedup 1.0000x reference)
#include <cuda_runtime.h>
#include <math.h>

#define PI_D 3.14159265358979323846

// ---------------------------------------------------------------------------
// SO(3) convolution, B=24 (grid 48), F_IN=F_OUT=16, BATCH=16, P=12 rotations.
// NSPEC = sum_{l<24} (2l+1)^2 = 18424, Z = 256.
// ---------------------------------------------------------------------------

namespace so3 {
constexpr int    NB     = 48;
constexpr int    NSPEC  = 18424;
constexpr int    NZ     = 256;
constexpr int    NUV    = NB * NB;          // 2304
constexpr int    NSLICE = NZ * NB;          // 12288
constexpr size_t SZW    = 48ull * NSPEC;    // 884352 floats per wigner stack
constexpr size_t OFF_WW = 0;                // weighted wigner (forward)
constexpr size_t OFF_WU = SZW;              // (2l+1)-scaled wigner (inverse)
constexpr size_t OFF_RFT = 2 * SZW;         // rft matrix, float2 [12][NSPEC]
constexpr size_t OFF_WF  = OFF_RFT + 2ull * 12 * NSPEC;  // DFT twiddles float2[48*48]
constexpr size_t TABSZ   = OFF_WF + 2ull * NUV;
constexpr float  SCALING = 0.07216878364870323f;  // 1/sqrt(12*16)
}
using namespace so3;

__device__ __forceinline__ int    base_l(int l) { return (4 * l * l * l - l) / 3; }
__device__ __forceinline__ size_t base3(int l)  { return (size_t)l * l * (2 * l * l - 1); }

__device__ __forceinline__ void cmac(float2& c, const float2 a, const float2 b) {
    c.x = fmaf(a.x, b.x, fmaf(-a.y, b.y, c.x));
    c.y = fmaf(a.x, b.y, fmaf( a.y, b.x, c.y));
}

// ------------------------- static device scratch ---------------------------
__device__ float  g_tab[TABSZ];                         // ~8.9 MB
__device__ double g_coef[662976];                       // wigner coefs, fp64
__device__ float2 g_X [(size_t)NZ * 48 * NUV];          // 226 MB (X, then S)
__device__ float2 g_Fx[(size_t)NSPEC * NZ];
__device__ float2 g_Fy[(size_t)NSPEC * NZ];
__device__ float2 g_Fz[(size_t)NSPEC * NZ];

// =============================== init ======================================

__global__ void k_init_wf() {
    int t = blockIdx.x * 256 + threadIdx.x;
    if (t < NUV) {
        int a = t / 48, b = t - 48 * a;
        double ang = -2.0 * PI_D * (double)(a * b) / 48.0;
        g_tab[OFF_WF + 2 * t]     = (float)cos(ang);
        g_tab[OFF_WF + 2 * t + 1] = (float)sin(ang);
    }
}

__global__ void k_init_coef() {
    int l = blockIdx.x;
    int L = 2 * l + 1;
    __shared__ double LNF[101];
    int t = threadIdx.x;
    for (int i = t; i < 101; i += 256) LNF[i] = lgamma((double)i + 1.0);
    __syncthreads();
    double* coef = g_coef + base3(l);
    for (int e = t; e < L * L; e += 256) {
        int i = e / L, jj = e - i * L;
        int mp = i - l, mm = jj - l;
        int kmin = max(0, mm - mp), kmax = min(l + mm, l - mp);
        for (int k = 0; k < L; k++) {
            double v = 0.0;
            if (k >= kmin && k <= kmax) {
                double ln = 0.5 * (LNF[l + mp] + LNF[l - mp] + LNF[l + mm] + LNF[l - mm])
                          - LNF[l + mm - k] - LNF[k] - LNF[mp - mm + k] - LNF[l - mp - k];
                v = exp(ln);
                if ((mp - mm + k) & 1) v = -v;
            }
            coef[(size_t)e * L + k] = v;
        }
    }
}

// jb < 48: SOFT beta grid (weighted + (2l+1)-scaled tables)
// jb = 48, 49: the two grid betas -> RFT matrix (with alpha phases)
__global__ void k_init_wig() {
    int l  = blockIdx.y;
    int L  = 2 * l + 1;
    int jb = blockIdx.x;
    __shared__ double cp[47], sp[47];
    __shared__ double sw;
    int t = threadIdx.x;
    if (t == 0) {
        double beta = (jb < 48) ? ((double)jb + 0.5) * PI_D / 48.0
                                : ((jb == 48) ? PI_D / 16.0 : PI_D / 8.0);
        double c = cos(beta * 0.5), s = sin(beta * 0.5);
        double pc = 1.0, ps = 1.0;
        for (int e = 0; e < 47; e++) { cp[e] = pc; sp[e] = ps; pc *= c; ps *= s; }
        if (jb < 48) {
            double ssum = 0.0;
            for (int k = 0; k < 24; k++)
                ssum += sin((double)(2 * jb + 1) * (double)(2 * k + 1) * PI_D / 96.0)
                        / (double)(2 * k + 1);
            sw = (2.0 / 24.0) * sin(PI_D * (double)(2 * jb + 1) / 96.0) * ssum * 0.5;
        } else {
            sw = 0.0;
        }
    }
    __syncthreads();
    const double* coef = g_coef + base3(l);
    size_t wb = 48ull * (size_t)base_l(l);
    for (int e = t; e < L * L; e += 256) {
        int i = e / L, jj = e - i * L;
        int mp = i - l, mm = jj - l;
        int kmin = max(0, mm - mp), kmax = min(l + mm, l - mp);
        double sum = 0.0;
        for (int k = kmin; k <= kmax; k++)
            sum += coef[(size_t)e * L + k] * cp[2 * l - 2 * k + mm - mp] * sp[2 * k + mp - mm];
        if (jb < 48) {
            size_t idx = wb + ((size_t)jb * L + i) * L + jj;
            g_tab[OFF_WW + idx] = (float)(sum * sw);
            g_tab[OFF_WU + idx] = (float)(sum * (double)(2 * l + 1));
        } else {
            int ib = jb - 48;
            size_t s = (size_t)base_l(l) + (size_t)i * L + jj;
            for (int ia = 0; ia < 6; ia++) {
                double ang = (double)mp * ((double)ia * (PI_D / 3.0));  // e^{+i m' alpha}
                int p = ia * 2 + ib;
                g_tab[OFF_RFT + 2 * ((size_t)p * NSPEC + s)]     = (float)(cos(ang) * sum);
                g_tab[OFF_RFT + 2 * ((size_t)p * NSPEC + s) + 1] = (float)(sin(ang) * sum);
            }
        }
    }
}

// ========================== forward 2-D DFT ================================
// X[z,j,u,v] = sum_{p,q} x[z,j,p,q] e^{-2pi i (up+vq)/48}

__global__ void __launch_bounds__(256) k_fft_fwd(const float* __restrict__ x) {
    __shared__ float  sx[NUV];
    __shared__ float2 sW[NUV];
    __shared__ float2 sT[NUV];
    int t = threadIdx.x;
    size_t slice = blockIdx.x;
    const float* xs = x + slice * NUV;
    const float2* Wf = (const float2*)(g_tab + OFF_WF);
    for (int i = t; i < NUV; i += 256) { sx[i] = xs[i]; sW[i] = Wf[i]; }
    __syncthreads();
    // stage A: T[p,v] = sum_q x[p,q] * W[q,v]   (real input, tiles 4p x 2v)
    for (int i = t; i < 288; i += 256) {
        int p0 = 4 * (i / 24), v0 = 2 * (i % 24);
        float2 acc[4][2];
#pragma unroll
        for (int a = 0; a < 4; a++)
#pragma unroll
            for (int b = 0; b < 2; b++) acc[a][b] = make_float2(0.f, 0.f);
#pragma unroll 4
        for (int q = 0; q < 48; q++) {
            float  a0 = sx[(p0 + 0) * 48 + q];
            float  a1 = sx[(p0 + 1) * 48 + q];
            float  a2 = sx[(p0 + 2) * 48 + q];
            float  a3 = sx[(p0 + 3) * 48 + q];
            float2 w0 = sW[q * 48 + v0];
            float2 w1 = sW[q * 48 + v0 + 1];
            acc[0][0].x = fmaf(a0, w0.x, acc[0][0].x); acc[0][0].y = fmaf(a0, w0.y, acc[0][0].y);
            acc[1][0].x = fmaf(a1, w0.x, acc[1][0].x); acc[1][0].y = fmaf(a1, w0.y, acc[1][0].y);
            acc[2][0].x = fmaf(a2, w0.x, acc[2][0].x); acc[2][0].y = fmaf(a2, w0.y, acc[2][0].y);
            acc[3][0].x = fmaf(a3, w0.x, acc[3][0].x); acc[3][0].y = fmaf(a3, w0.y, acc[3][0].y);
            acc[0][1].x = fmaf(a0, w1.x, acc[0][1].x); acc[0][1].y = fmaf(a0, w1.y, acc[0][1].y);
            acc[1][1].x = fmaf(a1, w1.x, acc[1][1].x); acc[1][1].y = fmaf(a1, w1.y, acc[1][1].y);
            acc[2][1].x = fmaf(a2, w1.x, acc[2][1].x); acc[2][1].y = fmaf(a2, w1.y, acc[2][1].y);
            acc[3][1].x = fmaf(a3, w1.x, acc[3][1].x); acc[3][1].y = fmaf(a3, w1.y, acc[3][1].y);
        }
#pragma unroll
        for (int a = 0; a < 4; a++)
#pragma unroll
            for (int b = 0; b < 2; b++) sT[(p0 + a) * 48 + v0 + b] = acc[a][b];
    }
    __syncthreads();
    // stage B: X[u,v] = sum_p T[p,v] * W[p,u]   (tiles 2u x 2v)
    float2* Xo = g_X + slice * NUV;
    for (int i = t; i < 576; i += 256) {
        int u0 = 2 * (i / 24), v0 = 2 * (i % 24);
        float2 c00 = make_float2(0.f, 0.f), c01 = c00, c10 = c00, c11 = c00;
#pragma unroll 4
        for (int p = 0; p < 48; p++) {
            float2 t0 = sT[p * 48 + v0];
            float2 t1 = sT[p * 48 + v0 + 1];
            float2 w0 = sW[p * 48 + u0];
            float2 w1 = sW[p * 48 + u0 + 1];
            cmac(c00, t0, w0);
            cmac(c01, t1, w0);
            cmac(c10, t0, w1);
            cmac(c11, t1, w1);
        }
        Xo[(u0 + 0) * 48 + v0 + 0] = c00;
        Xo[(u0 + 0) * 48 + v0 + 1] = c01;
        Xo[(u0 + 1) * 48 + v0 + 0] = c10;
        Xo[(u0 + 1) * 48 + v0 + 1] = c11;
    }
}

// ========================== beta contraction ===============================
// Fx[(l,su+l,sv+l), z] = sum_j wigW[l][j] * X[z,j,u,v]

__global__ void __launch_bounds__(256) k_contract() {
    int u = blockIdx.x, v = blockIdx.y;
    int su = (u < 24) ? u : u - 48;
    int sv = (v < 24) ? v : v - 48;
    if (su == -24 || sv == -24) return;
    int lmin = max(abs(su), abs(sv));
    __shared__ float ws[48 * 24];
    int t = threadIdx.x;
    for (int i = t; i < 48 * 24; i += 256) {
        int j = i / 24, l = i - 24 * j;
        float w = 0.f;
        if (l >= lmin) {
            int L = 2 * l + 1;
            w = g_tab[OFF_WW + 48ull * (size_t)base_l(l) + ((size_t)j * L + (su + l)) * L + (sv + l)];
        }
        ws[i] = w;
    }
    __syncthreads();
    float2 acc[24];
#pragma unroll
    for (int l = 0; l < 24; l++) acc[l] = make_float2(0.f, 0.f);
    const float2* Xp = g_X + (size_t)t * 48 * NUV + (size_t)u * 48 + v;  // z = t
    for (int j = 0; j < 48; j++) {
        float2 xv = Xp[(size_t)j * NUV];
        const float* wj = ws + j * 24;
#pragma unroll
        for (int l = 0; l < 24; l++) {
            float w = wj[l];
            acc[l].x = fmaf(w, xv.x, acc[l].x);
            acc[l].y = fmaf(w, xv.y, acc[l].y);
        }
    }
#pragma unroll
    for (int l = 0; l < 24; l++) {
        if (l >= lmin) {
            int L = 2 * l + 1;
            size_t s = (size_t)base_l(l) + (size_t)(su + l) * L + (sv + l);
            g_Fx[s * NZ + t] = acc[l];
        }
    }
}

// ================================ Fy ========================================
// Fy[s,f,g] = SCALING * sum_p kernel[f,g,p] * rft[p,s]

__global__ void __launch_bounds__(256) k_fy(const float* __restrict__ kern) {
    __shared__ float2 srft[12];
    int t = threadIdx.x;
    int f = t >> 4, g = t & 15;
    float kv[12];
#pragma unroll
    for (int p = 0; p < 12; p++) kv[p] = kern[(f * 16 + g) * 12 + p] * SCALING;
    const float2* rft = (const float2*)(g_tab + OFF_RFT);
    for (int s = blockIdx.x; s < NSPEC; s += gridDim.x) {
        if (t < 12) srft[t] = rft[(size_t)t * NSPEC + s];
        __syncthreads();
        float2 a = make_float2(0.f, 0.f);
#pragma unroll
        for (int p = 0; p < 12; p++) {
            a.x = fmaf(kv[p], srft[p].x, a.x);
            a.y = fmaf(kv[p], srft[p].y, a.y);
        }
        g_Fy[(size_t)s * NZ + t] = a;
        __syncthreads();
    }
}

// =============================== so3_mm ====================================
// Fz[(l,m,n),b,g] = sum_{k,f} Fx[(l,m,k),b,f] * Fy[(l,k,n),f,g]
// One block per 2x2 tile of (m,n); thread (b,g); smem-staged k loop.

__global__ void __launch_bounds__(256) k_mm(int l) {
    int L = 2 * l + 1;
    size_t base = (size_t)base_l(l);
    int m0 = 2 * blockIdx.x, n0 = 2 * blockIdx.y;
    bool m1ok = (m0 + 1) < L, n1ok = (n0 + 1) < L;
    __shared__ float2 Xs[2][256], Ys[2][256];
    int t = threadIdx.x;
    int b = t >> 4, g = t & 15;
    float2 c00 = make_float2(0.f, 0.f), c01 = c00, c10 = c00, c11 = c00;
    for (int k = 0; k < L; k++) {
        Xs[0][t] = g_Fx[(base + (size_t)m0 * L + k) * NZ + t];
        Xs[1][t] = m1ok ? g_Fx[(base + (size_t)(m0 + 1) * L + k) * NZ + t] : make_float2(0.f, 0.f);
        Ys[0][t] = g_Fy[(base + (size_t)k * L + n0) * NZ + t];
        Ys[1][t] = n1ok ? g_Fy[(base + (size_t)k * L + n0 + 1) * NZ + t] : make_float2(0.f, 0.f);
        __syncthreads();
#pragma unroll
        for (int f = 0; f < 16; f++) {
            float2 x0 = Xs[0][b * 16 + f];
            float2 x1 = Xs[1][b * 16 + f];
            float2 y0 = Ys[0][f * 16 + g];
            float2 y1 = Ys[1][f * 16 + g];
            cmac(c00, x0, y0);
            cmac(c01, x0, y1);
            cmac(c10, x1, y0);
            cmac(c11, x1, y1);
        }
        __syncthreads();
    }
    size_t s00 = base + (size_t)m0 * L + n0;
    g_Fz[s00 * NZ + t] = c00;
    if (n1ok) g_Fz[(s00 + 1) * NZ + t] = c01;
    if (m1ok) g_Fz[(base + (size_t)(m0 + 1) * L + n0) * NZ + t] = c10;
    if (m1ok && n1ok) g_Fz[(base + (size_t)(m0 + 1) * L + n0 + 1) * NZ + t] = c11;
}

// =============================== expand ====================================
// S[z,j,u,v] = sum_l wigU[l][j,su+l,sv+l] * Fz[(l,su+l,sv+l), z]   (S -> g_X)

__global__ void __launch_bounds__(256) k_expand() {
    int u = blockIdx.x, v = blockIdx.y;
    int su = (u < 24) ? u : u - 48;
    int sv = (v < 24) ? v : v - 48;
    int t = threadIdx.x;
    float2* Sp = g_X + (size_t)t * 48 * NUV + (size_t)u * 48 + v;  // z = t
    if (su == -24 || sv == -24) {
        for (int j = 0; j < 48; j++) Sp[(size_t)j * NUV] = make_float2(0.f, 0.f);
        return;
    }
    int lmin = max(abs(su), abs(sv));
    __shared__ float ws[48 * 24];
    for (int i = t; i < 48 * 24; i += 256) {
        int j = i / 24, l = i - 24 * j;
        float w = 0.f;
        if (l >= lmin) {
            int L = 2 * l + 1;
            w = g_tab[OFF_WU + 48ull * (size_t)base_l(l) + ((size_t)j * L + (su + l)) * L + (sv + l)];
        }
        ws[i] = w;
    }
    __syncthreads();
    float2 fv[24];
#pragma unroll
    for (int l = 0; l < 24; l++) {
        fv[l] = make_float2(0.f, 0.f);
        if (l >= lmin) {
            int L = 2 * l + 1;
            size_t s = (size_t)base_l(l) + (size_t)(su + l) * L + (sv + l);
            fv[l] = g_Fz[s * NZ + t];
        }
    }
    for (int j = 0; j < 48; j++) {
        const float* wj = ws + j * 24;
        float2 a = make_float2(0.f, 0.f);
#pragma unroll
        for (int l = 0; l < 24; l++) {
            a.x = fmaf(wj[l], fv[l].x, a.x);
            a.y = fmaf(wj[l], fv[l].y, a.y);
        }
        Sp[(size_t)j * NUV] = a;
    }
}

// ========================== inverse 2-D DFT ================================
// out[z,j,p,q] = Re( sum_{u,v} S[u,v] e^{+2pi i (up+vq)/48} ) / 2304

__global__ void __launch_bounds__(256) k_fft_inv(float* __restrict__ out) {
    __shared__ float2 sS[NUV];
    __shared__ float2 sW[NUV];
    int t = threadIdx.x;
    size_t slice = blockIdx.x;
    const float2* Sp = g_X + slice * NUV;
    const float2* Wf = (const float2*)(g_tab + OFF_WF);
    for (int i = t; i < NUV; i += 256) { sS[i] = Sp[i]; sW[i] = Wf[i]; }
    __syncthreads();
    // stage A into registers: T[u,q] = sum_v S[u,v] * conj(W[v,q]); tiles 2x2
    float2 cc[3][4];
#pragma unroll
    for (int it = 0; it < 3; it++) {
        int i = t + it * 256;
#pragma unroll
        for (int a = 0; a < 4; a++) cc[it][a] = make_float2(0.f, 0.f);
        if (i < 576) {
            int u0 = 2 * (i / 24), q0 = 2 * (i % 24);
#pragma unroll 4
            for (int v = 0; v < 48; v++) {
                float2 s0 = sS[(u0 + 0) * 48 + v];
                float2 s1 = sS[(u0 + 1) * 48 + v];
                float2 w0 = sW[v * 48 + q0];
                float2 w1 = sW[v * 48 + q0 + 1];
                // S * conj(W): re = sx*wx + sy*wy ; im = sy*wx - sx*wy
                cc[it][0].x = fmaf(s0.x, w0.x, fmaf( s0.y, w0.y, cc[it][0].x));
                cc[it][0].y = fmaf(s0.y, w0.x, fmaf(-s0.x, w0.y, cc[it][0].y));
                cc[it][1].x = fmaf(s0.x, w1.x, fmaf( s0.y, w1.y, cc[it][1].x));
                cc[it][1].y = fmaf(s0.y, w1.x, fmaf(-s0.x, w1.y, cc[it][1].y));
                cc[it][2].x = fmaf(s1.x, w0.x, fmaf( s1.y, w0.y, cc[it][2].x));
                cc[it][2].y = fmaf(s1.y, w0.x, fmaf(-s1.x, w0.y, cc[it][2].y));
                cc[it][3].x = fmaf(s1.x, w1.x, fmaf( s1.y, w1.y, cc[it][3].x));
                cc[it][3].y = fmaf(s1.y, w1.x, fmaf(-s1.x, w1.y, cc[it][3].y));
            }
        }
    }
    __syncthreads();  // all sS reads done; reuse sS to hold T
#pragma unroll
    for (int it = 0; it < 3; it++) {
        int i = t + it * 256;
        if (i < 576) {
            int u0 = 2 * (i / 24), q0 = 2 * (i % 24);
            sS[(u0 + 0) * 48 + q0 + 0] = cc[it][0];
            sS[(u0 + 0) * 48 + q0 + 1] = cc[it][1];
            sS[(u0 + 1) * 48 + q0 + 0] = cc[it][2];
            sS[(u0 + 1) * 48 + q0 + 1] = cc[it][3];
        }
    }
    __syncthreads();
    // stage B: out[p,q] = (sum_u T.x*W[u,p].x + T.y*W[u,p].y) / 2304; tiles 4x4
    float* op = out + slice * NUV;
    if (t < 144) {
        int p0 = 4 * (t / 12), q0 = 4 * (t % 12);
        float r[4][4];
#pragma unroll
        for (int a = 0; a < 4; a++)
#pragma unroll
            for (int b = 0; b < 4; b++) r[a][b] = 0.f;
#pragma unroll 2
        for (int u = 0; u < 48; u++) {
            float2 tw[4], wv[4];
#pragma unroll
            for (int b = 0; b < 4; b++) tw[b] = sS[u * 48 + q0 + b];
#pragma unroll
            for (int a = 0; a < 4; a++) wv[a] = sW[u * 48 + p0 + a];
#pragma unroll
            for (int a = 0; a < 4; a++)
#pragma unroll
                for (int b = 0; b < 4; b++)
                    r[a][b] = fmaf(tw[b].x, wv[a].x, fmaf(tw[b].y, wv[a].y, r[a][b]));
        }
        const float scale = 1.f / 2304.f;
#pragma unroll
        for (int a = 0; a < 4; a++)
#pragma unroll
            for (int b = 0; b < 4; b++)
                op[(p0 + a) * 48 + q0 + b] = r[a][b] * scale;
    }
}

// ============================== launch ======================================

extern "C" void kernel_launch(void* const* d_in, const int* in_sizes, int n_in,
                              void* d_out, int out_size) {
    const float* x    = (const float*)d_in[0];
    const float* kern = (const float*)d_in[1];
    if (n_in >= 2 && in_sizes[0] == 16 * 16 * 12) {  // robustness to input order
        x = (const float*)d_in[1];
        kern = (const float*)d_in[0];
    }
    float* out = (float*)d_out;

    k_init_wf  <<<9, 256>>>();
    k_init_coef<<<24, 256>>>();
    k_init_wig <<<dim3(50, 24), 256>>>();

    k_fft_fwd  <<<NSLICE, 256>>>(x);
    k_contract <<<dim3(48, 48), 256>>>();
    k_fy       <<<512, 256>>>(kern);
    for (int l = 0; l < 24; l++) {
        int nt = l + 1;  // ceil((2l+1)/2)
        k_mm<<<dim3(nt, nt), 256>>>(l);
    }
    k_expand   <<<dim3(48, 48), 256>>>();
    k_fft_inv  <<<NSLICE, 256>>>(out);
}

// round 9
// speedup vs baseline: 1.3806x; 1.3806x over previous
#include <cuda_runtime.h>
#include <math.h>

#define PI_D 3.14159265358979323846

// ---------------------------------------------------------------------------
// SO(3) convolution, B=24 (grid 48), F_IN=F_OUT=16, BATCH=16, P=12 rotations.
// NSPEC = sum_{l<24} (2l+1)^2 = 18424, Z = 256.
// ---------------------------------------------------------------------------

namespace so3 {
constexpr int    NB     = 48;
constexpr int    NSPEC  = 18424;
constexpr int    NZ     = 256;
constexpr int    NUV    = NB * NB;          // 2304
constexpr int    NSLICE = NZ * NB;          // 12288
constexpr size_t SZW    = 48ull * NSPEC;    // floats per wigner stack
constexpr size_t OFF_WW = 0;                // weighted wigner (forward)
constexpr size_t OFF_WU = SZW;              // (2l+1)-scaled wigner (inverse)
constexpr size_t OFF_RFT = 2 * SZW;         // rft matrix, float2 [12][NSPEC]
constexpr size_t OFF_WF  = OFF_RFT + 2ull * 12 * NSPEC;  // DFT twiddles float2[48*48]
constexpr size_t TABSZ   = OFF_WF + 2ull * NUV;
constexpr float  SCALING = 0.07216878364870323f;  // 1/sqrt(12*16)
}
using namespace so3;

__device__ __forceinline__ int    base_l(int l) { return (4 * l * l * l - l) / 3; }
__device__ __forceinline__ size_t base3(int l)  { return (size_t)l * l * (2 * l * l - 1); }

__device__ __forceinline__ void cmac(float2& c, const float2 a, const float2 b) {
    c.x = fmaf(a.x, b.x, fmaf(-a.y, b.y, c.x));
    c.y = fmaf(a.x, b.y, fmaf( a.y, b.x, c.y));
}

// ------------------------- static device scratch ---------------------------
__device__ float  g_tab[TABSZ];                          // ~8.9 MB
__device__ double g_coef[662976];                        // wigner coefs, fp64
__device__ float4 g_X4[(size_t)NZ * 48 * NUV / 2];       // 226 MB (X, then S)
__device__ float2 g_Fx[(size_t)NSPEC * NZ];
__device__ float2 g_Fy[(size_t)NSPEC * NZ];
__device__ float2 g_Fz[(size_t)NSPEC * NZ];

// =============================== init ======================================

__global__ void k_init_wf() {
    int t = blockIdx.x * 256 + threadIdx.x;
    if (t < NUV) {
        int a = t / 48, b = t - 48 * a;
        double ang = -2.0 * PI_D * (double)(a * b) / 48.0;
        g_tab[OFF_WF + 2 * t]     = (float)cos(ang);
        g_tab[OFF_WF + 2 * t + 1] = (float)sin(ang);
    }
}

// Only canonical quadrant (i <= jj, i + jj <= L-1) is ever read by k_init_wig.
__global__ void k_init_coef() {
    int l = blockIdx.x;
    int L = 2 * l + 1;
    __shared__ double LNF[101];
    int t = threadIdx.x;
    for (int i = t; i < 101; i += 256) LNF[i] = lgamma((double)i + 1.0);
    __syncthreads();
    double* coef = g_coef + base3(l);
    for (int e = t; e < L * L; e += 256) {
        int i = e / L, jj = e - i * L;
        if (i > jj || i + jj > L - 1) continue;   // canonical only
        int mp = i - l, mm = jj - l;
        int kmin = max(0, mm - mp), kmax = min(l + mm, l - mp);
        for (int k = kmin; k <= kmax; k++) {
            double ln = 0.5 * (LNF[l + mp] + LNF[l - mp] + LNF[l + mm] + LNF[l - mm])
                      - LNF[l + mm - k] - LNF[k] - LNF[mp - mm + k] - LNF[l - mp - k];
            double v = exp(ln);
            if ((mp - mm + k) & 1) v = -v;
            coef[(size_t)e * L + k] = v;
        }
    }
}

// jb < 48: SOFT beta grid (weighted + (2l+1)-scaled tables)
// jb = 48, 49: the two grid betas -> RFT matrix (with exact pi/3 alpha phases)
// 4-fold symmetry: d_{m'm} = sigma d_{mm'} = sigma d_{-m'-m} = d wait.. see below
//   (i,jj)=V  (jj,i)=sigma V  (L-1-i,L-1-jj)=sigma V  (L-1-jj,L-1-i)=V,
//   sigma = (-1)^{i-jj}
__global__ void k_init_wig() {
    int l  = blockIdx.y;
    int L  = 2 * l + 1;
    int jb = blockIdx.x;
    __shared__ double cp[47], sp[47];
    __shared__ double sw;
    int t = threadIdx.x;
    if (t == 0) {
        double beta = (jb < 48) ? ((double)jb + 0.5) * PI_D / 48.0
                                : ((jb == 48) ? PI_D / 16.0 : PI_D / 8.0);
        double c = cos(beta * 0.5), s = sin(beta * 0.5);
        double pc = 1.0, ps = 1.0;
        for (int e = 0; e < 47; e++) { cp[e] = pc; sp[e] = ps; pc *= c; ps *= s; }
        if (jb < 48) {
            double ssum = 0.0;
            for (int k = 0; k < 24; k++)
                ssum += sin((double)(2 * jb + 1) * (double)(2 * k + 1) * PI_D / 96.0)
                        / (double)(2 * k + 1);
            sw = (2.0 / 24.0) * sin(PI_D * (double)(2 * jb + 1) / 96.0) * ssum * 0.5;
        } else {
            sw = 0.0;
        }
    }
    __syncthreads();
    const double CT6[6] = {1.0, 0.5, -0.5, -1.0, -0.5, 0.5};
    const double ST6[6] = {0.0,  0.8660254037844386,  0.8660254037844386,
                           0.0, -0.8660254037844386, -0.8660254037844386};
    const double* coef = g_coef + base3(l);
    size_t wb = 48ull * (size_t)base_l(l);
    for (int e = t; e < L * L; e += 256) {
        int i = e / L, jj = e - i * L;
        if (i > jj || i + jj > L - 1) continue;   // canonical quadrant
        int mp = i - l, mm = jj - l;
        int kmin = max(0, mm - mp), kmax = min(l + mm, l - mp);
        double sum = 0.0;
        for (int k = kmin; k <= kmax; k++)
            sum += coef[(size_t)e * L + k] * cp[2 * l - 2 * k + mm - mp] * sp[2 * k + mp - mm];
        double sgn = ((i - jj) & 1) ? -sum : sum;
        int    rr[4]  = { i, jj, L - 1 - i, L - 1 - jj };
        int    ccn[4] = { jj, i, L - 1 - jj, L - 1 - i };
        double vl[4]  = { sum, sgn, sgn, sum };
        if (jb < 48) {
#pragma unroll
            for (int q = 0; q < 4; q++) {
                size_t idx = wb + ((size_t)jb * L + rr[q]) * L + ccn[q];
                g_tab[OFF_WW + idx] = (float)(vl[q] * sw);
                g_tab[OFF_WU + idx] = (float)(vl[q] * (double)L);
            }
        } else {
            int ib = jb - 48;
#pragma unroll
            for (int q = 0; q < 4; q++) {
                size_t s = (size_t)base_l(l) + (size_t)rr[q] * L + ccn[q];
                int mpr = rr[q] - l;
                for (int ia = 0; ia < 6; ia++) {
                    int n = ((mpr * ia) % 6 + 6) % 6;
                    int p = ia * 2 + ib;
                    g_tab[OFF_RFT + 2 * ((size_t)p * NSPEC + s)]     = (float)(CT6[n] * vl[q]);
                    g_tab[OFF_RFT + 2 * ((size_t)p * NSPEC + s) + 1] = (float)(ST6[n] * vl[q]);
                }
            }
        }
    }
}

// ========================== forward 2-D DFT ================================

__global__ void __launch_bounds__(256) k_fft_fwd(const float* __restrict__ x) {
    __shared__ float  sx[NUV];
    __shared__ float2 sW[NUV];
    __shared__ float2 sT[NUV];
    int t = threadIdx.x;
    size_t slice = blockIdx.x;
    const float* xs = x + slice * NUV;
    const float2* Wf = (const float2*)(g_tab + OFF_WF);
    for (int i = t; i < NUV; i += 256) { sx[i] = xs[i]; sW[i] = Wf[i]; }
    __syncthreads();
    // stage A: T[p,v] = sum_q x[p,q] * W[q,v]   (real input, tiles 4p x 2v)
    for (int i = t; i < 288; i += 256) {
        int p0 = 4 * (i / 24), v0 = 2 * (i % 24);
        float2 acc[4][2];
#pragma unroll
        for (int a = 0; a < 4; a++)
#pragma unroll
            for (int b = 0; b < 2; b++) acc[a][b] = make_float2(0.f, 0.f);
#pragma unroll 4
        for (int q = 0; q < 48; q++) {
            float  a0 = sx[(p0 + 0) * 48 + q];
            float  a1 = sx[(p0 + 1) * 48 + q];
            float  a2 = sx[(p0 + 2) * 48 + q];
            float  a3 = sx[(p0 + 3) * 48 + q];
            float2 w0 = sW[q * 48 + v0];
            float2 w1 = sW[q * 48 + v0 + 1];
            acc[0][0].x = fmaf(a0, w0.x, acc[0][0].x); acc[0][0].y = fmaf(a0, w0.y, acc[0][0].y);
            acc[1][0].x = fmaf(a1, w0.x, acc[1][0].x); acc[1][0].y = fmaf(a1, w0.y, acc[1][0].y);
            acc[2][0].x = fmaf(a2, w0.x, acc[2][0].x); acc[2][0].y = fmaf(a2, w0.y, acc[2][0].y);
            acc[3][0].x = fmaf(a3, w0.x, acc[3][0].x); acc[3][0].y = fmaf(a3, w0.y, acc[3][0].y);
            acc[0][1].x = fmaf(a0, w1.x, acc[0][1].x); acc[0][1].y = fmaf(a0, w1.y, acc[0][1].y);
            acc[1][1].x = fmaf(a1, w1.x, acc[1][1].x); acc[1][1].y = fmaf(a1, w1.y, acc[1][1].y);
            acc[2][1].x = fmaf(a2, w1.x, acc[2][1].x); acc[2][1].y = fmaf(a2, w1.y, acc[2][1].y);
            acc[3][1].x = fmaf(a3, w1.x, acc[3][1].x); acc[3][1].y = fmaf(a3, w1.y, acc[3][1].y);
        }
#pragma unroll
        for (int a = 0; a < 4; a++)
#pragma unroll
            for (int b = 0; b < 2; b++) sT[(p0 + a) * 48 + v0 + b] = acc[a][b];
    }
    __syncthreads();
    // stage B: X[u,v] = sum_p T[p,v] * W[p,u]   (tiles 2u x 2v)
    float2* Xo = (float2*)g_X4 + slice * NUV;
    for (int i = t; i < 576; i += 256) {
        int u0 = 2 * (i / 24), v0 = 2 * (i % 24);
        float2 c00 = make_float2(0.f, 0.f), c01 = c00, c10 = c00, c11 = c00;
#pragma unroll 4
        for (int p = 0; p < 48; p++) {
            float2 t0 = sT[p * 48 + v0];
            float2 t1 = sT[p * 48 + v0 + 1];
            float2 w0 = sW[p * 48 + u0];
            float2 w1 = sW[p * 48 + u0 + 1];
            cmac(c00, t0, w0);
            cmac(c01, t1, w0);
            cmac(c10, t0, w1);
            cmac(c11, t1, w1);
        }
        Xo[(u0 + 0) * 48 + v0 + 0] = c00;
        Xo[(u0 + 0) * 48 + v0 + 1] = c01;
        Xo[(u0 + 1) * 48 + v0 + 0] = c10;
        Xo[(u0 + 1) * 48 + v0 + 1] = c11;
    }
}

// ========================== beta contraction ===============================
// Fx[(l,su+l,sv+l), z] = sum_j wigW[l][j] * X[z,j,u,v]
// Block: (half of l-range, u, v-pair). Thread = z. float4 loads (2 v's).

__global__ void __launch_bounds__(256) k_contract() {
    int half = blockIdx.x;            // l in [12*half, 12*half+12)
    int u  = blockIdx.y;
    int v0 = 2 * blockIdx.z;
    int su = (u < 24) ? u : u - 48;
    bool uok = (su != -24);
    int l0 = 12 * half;
    int lmin[2];
#pragma unroll
    for (int vv = 0; vv < 2; vv++) {
        int v = v0 + vv;
        int sv = (v < 24) ? v : v - 48;
        lmin[vv] = (uok && sv != -24) ? max(abs(su), abs(sv)) : 24;
    }
    __shared__ __align__(16) float ws[48][24];   // [j][2*(l-l0)+vv]
    int t = threadIdx.x;
    for (int i = t; i < 48 * 24; i += 256) {
        int j = i / 24, r = i - 24 * j;
        int dl = r >> 1, vv = r & 1;
        int l = l0 + dl;
        float w = 0.f;
        if (l >= lmin[vv]) {
            int L = 2 * l + 1;
            int v = v0 + vv;
            int sv = (v < 24) ? v : v - 48;
            w = g_tab[OFF_WW + 48ull * (size_t)base_l(l) + ((size_t)j * L + (su + l)) * L + (sv + l)];
        }
        ws[j][r] = w;
    }
    __syncthreads();
    float4 acc[12];
#pragma unroll
    for (int d = 0; d < 12; d++) acc[d] = make_float4(0.f, 0.f, 0.f, 0.f);
    const float4* Xp = g_X4 + ((size_t)t * 48 * NUV + (size_t)u * 48 + v0) / 2;
#pragma unroll 8
    for (int j = 0; j < 48; j++) {
        float4 xv = Xp[(size_t)j * (NUV / 2)];
        const float2* wj = (const float2*)ws[j];
#pragma unroll
        for (int d = 0; d < 12; d++) {
            float2 w = wj[d];
            acc[d].x = fmaf(w.x, xv.x, acc[d].x);
            acc[d].y = fmaf(w.x, xv.y, acc[d].y);
            acc[d].z = fmaf(w.y, xv.z, acc[d].z);
            acc[d].w = fmaf(w.y, xv.w, acc[d].w);
        }
    }
#pragma unroll
    for (int d = 0; d < 12; d++) {
        int l = l0 + d;
        int L = 2 * l + 1;
        size_t bs = (size_t)base_l(l);
        if (l >= lmin[0]) {
            int sv = (v0 < 24) ? v0 : v0 - 48;
            g_Fx[(bs + (size_t)(su + l) * L + (sv + l)) * NZ + t] = make_float2(acc[d].x, acc[d].y);
        }
        if (l >= lmin[1]) {
            int v = v0 + 1;
            int sv = (v < 24) ? v : v - 48;
            g_Fx[(bs + (size_t)(su + l) * L + (sv + l)) * NZ + t] = make_float2(acc[d].z, acc[d].w);
        }
    }
}

// ================================ Fy ========================================

__global__ void __launch_bounds__(256) k_fy(const float* __restrict__ kern) {
    __shared__ float2 srft[12];
    int t = threadIdx.x;
    int f = t >> 4, g = t & 15;
    float kv[12];
#pragma unroll
    for (int p = 0; p < 12; p++) kv[p] = kern[(f * 16 + g) * 12 + p] * SCALING;
    const float2* rft = (const float2*)(g_tab + OFF_RFT);
    for (int s = blockIdx.x; s < NSPEC; s += gridDim.x) {
        if (t < 12) srft[t] = rft[(size_t)t * NSPEC + s];
        __syncthreads();
        float2 a = make_float2(0.f, 0.f);
#pragma unroll
        for (int p = 0; p < 12; p++) {
            a.x = fmaf(kv[p], srft[p].x, a.x);
            a.y = fmaf(kv[p], srft[p].y, a.y);
        }
        g_Fy[(size_t)s * NZ + t] = a;
        __syncthreads();
    }
}

// =============================== so3_mm ====================================
// Fz[(l,m,n),b,g] = sum_{k,f} Fx[(l,m,k),b,f] * Fy[(l,k,n),f,g]
// ONE launch: blockIdx.z = l, 4x4 tile of (m,n); thread (b,g); smem k loop.

__global__ void __launch_bounds__(256) k_mm_all() {
    int l = blockIdx.z;
    int L = 2 * l + 1;
    int n0 = 4 * blockIdx.x;
    int m0 = 4 * blockIdx.y;
    if (m0 >= L || n0 >= L) return;
    size_t base = (size_t)base_l(l);
    __shared__ float2 Xs[4][256], Ys[4][256];
    int t = threadIdx.x;
    int b = t >> 4, g = t & 15;
    float2 c[4][4];
#pragma unroll
    for (int a = 0; a < 4; a++)
#pragma unroll
        for (int bb = 0; bb < 4; bb++) c[a][bb] = make_float2(0.f, 0.f);
    const float2 z2 = make_float2(0.f, 0.f);
    for (int k = 0; k < L; k++) {
#pragma unroll
        for (int a = 0; a < 4; a++) {
            Xs[a][t] = (m0 + a < L) ? g_Fx[(base + (size_t)(m0 + a) * L + k) * NZ + t] : z2;
            Ys[a][t] = (n0 + a < L) ? g_Fy[(base + (size_t)k * L + (n0 + a)) * NZ + t] : z2;
        }
        __syncthreads();
#pragma unroll
        for (int f = 0; f < 16; f++) {
            float2 xr[4], yr[4];
#pragma unroll
            for (int a = 0; a < 4; a++) { xr[a] = Xs[a][b * 16 + f]; yr[a] = Ys[a][f * 16 + g]; }
#pragma unroll
            for (int a = 0; a < 4; a++)
#pragma unroll
                for (int bb = 0; bb < 4; bb++) cmac(c[a][bb], xr[a], yr[bb]);
        }
        __syncthreads();
    }
#pragma unroll
    for (int a = 0; a < 4; a++) {
        if (m0 + a >= L) continue;
#pragma unroll
        for (int bb = 0; bb < 4; bb++) {
            if (n0 + bb >= L) continue;
            g_Fz[(base + (size_t)(m0 + a) * L + (n0 + bb)) * NZ + t] = c[a][bb];
        }
    }
}

// =============================== expand ====================================
// S[z,j,u,v] = sum_l wigU[l][j,su+l,sv+l] * Fz[(l,su+l,sv+l), z]  (S -> g_X4)
// Block: (u, v-pair). Thread = z. float4 stores (2 v's).

__global__ void __launch_bounds__(256) k_expand() {
    int u  = blockIdx.x;
    int v0 = 2 * blockIdx.y;
    int su = (u < 24) ? u : u - 48;
    bool uok = (su != -24);
    int t = threadIdx.x;
    int lmin[2];
#pragma unroll
    for (int vv = 0; vv < 2; vv++) {
        int v = v0 + vv;
        int sv = (v < 24) ? v : v - 48;
        lmin[vv] = (uok && sv != -24) ? max(abs(su), abs(sv)) : 24;
    }
    __shared__ __align__(16) float ws[48][48];   // [j][2*l+vv]
    for (int i = t; i < 48 * 48; i += 256) {
        int j = i / 48, r = i - 48 * j;
        int l = r >> 1, vv = r & 1;
        float w = 0.f;
        if (l >= lmin[vv]) {
            int L = 2 * l + 1;
            int v = v0 + vv;
            int sv = (v < 24) ? v : v - 48;
            w = g_tab[OFF_WU + 48ull * (size_t)base_l(l) + ((size_t)j * L + (su + l)) * L + (sv + l)];
        }
        ws[j][r] = w;
    }
    __syncthreads();
    float4 fv[24];
#pragma unroll
    for (int l = 0; l < 24; l++) {
        fv[l] = make_float4(0.f, 0.f, 0.f, 0.f);
        int L = 2 * l + 1;
        size_t bs = (size_t)base_l(l);
        if (l >= lmin[0]) {
            int sv = (v0 < 24) ? v0 : v0 - 48;
            float2 f2 = g_Fz[(bs + (size_t)(su + l) * L + (sv + l)) * NZ + t];
            fv[l].x = f2.x; fv[l].y = f2.y;
        }
        if (l >= lmin[1]) {
            int v = v0 + 1;
            int sv = (v < 24) ? v : v - 48;
            float2 f2 = g_Fz[(bs + (size_t)(su + l) * L + (sv + l)) * NZ + t];
            fv[l].z = f2.x; fv[l].w = f2.y;
        }
    }
    float4* Sp = g_X4 + ((size_t)t * 48 * NUV + (size_t)u * 48 + v0) / 2;
#pragma unroll 4
    for (int j = 0; j < 48; j++) {
        const float2* wj = (const float2*)ws[j];
        float4 a = make_float4(0.f, 0.f, 0.f, 0.f);
#pragma unroll
        for (int l = 0; l < 24; l++) {
            float2 w = wj[l];
            a.x = fmaf(w.x, fv[l].x, a.x);
            a.y = fmaf(w.x, fv[l].y, a.y);
            a.z = fmaf(w.y, fv[l].z, a.z);
            a.w = fmaf(w.y, fv[l].w, a.w);
        }
        Sp[(size_t)j * (NUV / 2)] = a;
    }
}

// ========================== inverse 2-D DFT ================================

__global__ void __launch_bounds__(256) k_fft_inv(float* __restrict__ out) {
    __shared__ float2 sS[NUV];
    __shared__ float2 sW[NUV];
    int t = threadIdx.x;
    size_t slice = blockIdx.x;
    const float2* Sp = (const float2*)g_X4 + slice * NUV;
    const float2* Wf = (const float2*)(g_tab + OFF_WF);
    for (int i = t; i < NUV; i += 256) { sS[i] = Sp[i]; sW[i] = Wf[i]; }
    __syncthreads();
    float2 cc[3][4];
#pragma unroll
    for (int it = 0; it < 3; it++) {
        int i = t + it * 256;
#pragma unroll
        for (int a = 0; a < 4; a++) cc[it][a] = make_float2(0.f, 0.f);
        if (i < 576) {
            int u0 = 2 * (i / 24), q0 = 2 * (i % 24);
#pragma unroll 4
            for (int v = 0; v < 48; v++) {
                float2 s0 = sS[(u0 + 0) * 48 + v];
                float2 s1 = sS[(u0 + 1) * 48 + v];
                float2 w0 = sW[v * 48 + q0];
                float2 w1 = sW[v * 48 + q0 + 1];
                cc[it][0].x = fmaf(s0.x, w0.x, fmaf( s0.y, w0.y, cc[it][0].x));
                cc[it][0].y = fmaf(s0.y, w0.x, fmaf(-s0.x, w0.y, cc[it][0].y));
                cc[it][1].x = fmaf(s0.x, w1.x, fmaf( s0.y, w1.y, cc[it][1].x));
                cc[it][1].y = fmaf(s0.y, w1.x, fmaf(-s0.x, w1.y, cc[it][1].y));
                cc[it][2].x = fmaf(s1.x, w0.x, fmaf( s1.y, w0.y, cc[it][2].x));
                cc[it][2].y = fmaf(s1.y, w0.x, fmaf(-s1.x, w0.y, cc[it][2].y));
                cc[it][3].x = fmaf(s1.x, w1.x, fmaf( s1.y, w1.y, cc[it][3].x));
                cc[it][3].y = fmaf(s1.y, w1.x, fmaf(-s1.x, w1.y, cc[it][3].y));
            }
        }
    }
    __syncthreads();
#pragma unroll
    for (int it = 0; it < 3; it++) {
        int i = t + it * 256;
        if (i < 576) {
            int u0 = 2 * (i / 24), q0 = 2 * (i % 24);
            sS[(u0 + 0) * 48 + q0 + 0] = cc[it][0];
            sS[(u0 + 0) * 48 + q0 + 1] = cc[it][1];
            sS[(u0 + 1) * 48 + q0 + 0] = cc[it][2];
            sS[(u0 + 1) * 48 + q0 + 1] = cc[it][3];
        }
    }
    __syncthreads();
    float* op = out + slice * NUV;
    if (t < 144) {
        int p0 = 4 * (t / 12), q0 = 4 * (t % 12);
        float r[4][4];
#pragma unroll
        for (int a = 0; a < 4; a++)
#pragma unroll
            for (int b = 0; b < 4; b++) r[a][b] = 0.f;
#pragma unroll 2
        for (int u = 0; u < 48; u++) {
            float2 tw[4], wv[4];
#pragma unroll
            for (int b = 0; b < 4; b++) tw[b] = sS[u * 48 + q0 + b];
#pragma unroll
            for (int a = 0; a < 4; a++) wv[a] = sW[u * 48 + p0 + a];
#pragma unroll
            for (int a = 0; a < 4; a++)
#pragma unroll
                for (int b = 0; b < 4; b++)
                    r[a][b] = fmaf(tw[b].x, wv[a].x, fmaf(tw[b].y, wv[a].y, r[a][b]));
        }
        const float scale = 1.f / 2304.f;
#pragma unroll
        for (int a = 0; a < 4; a++)
#pragma unroll
            for (int b = 0; b < 4; b++)
                op[(p0 + a) * 48 + q0 + b] = r[a][b] * scale;
    }
}

// ============================== launch ======================================

extern "C" void kernel_launch(void* const* d_in, const int* in_sizes, int n_in,
                              void* d_out, int out_size) {
    const float* x    = (const float*)d_in[0];
    const float* kern = (const float*)d_in[1];
    if (n_in >= 2 && in_sizes[0] == 16 * 16 * 12) {
        x = (const float*)d_in[1];
        kern = (const float*)d_in[0];
    }
    float* out = (float*)d_out;

    k_init_wf  <<<9, 256>>>();
    k_init_coef<<<24, 256>>>();
    k_init_wig <<<dim3(50, 24), 256>>>();

    k_fft_fwd  <<<NSLICE, 256>>>(x);
    k_contract <<<dim3(2, 48, 24), 256>>>();
    k_fy       <<<512, 256>>>(kern);
    k_mm_all   <<<dim3(12, 12, 24), 256>>>();
    k_expand   <<<dim3(48, 24), 256>>>();
    k_fft_inv  <<<NSLICE, 256>>>(out);
}